// round 3
// baseline (speedup 1.0000x reference)
#include <cuda_runtime.h>

// GAE backward scan, fully parallel over T via affine-map suffix composition.
//
// gae_t = d_t + m_t * gae_{t+1},  m_t = GAMMA*LMBDA*(1-term_t)  (binary: 0 or GL)
// d_t   = r_t + GAMMA*nv_t*(1-term_t) - v_t
// adv = gae ; ret = gae + v
//
// Layout: (B=8192, T=256, A=4). One float4 = one (b,t) across 4 agents.
// Per block: BB=8 sequences, all 256 timesteps at once.
// Scan threads: one per (b_local, agent, chunk-of-32) = 8*4*8 = 256 threads.
// Chunk affine maps composed across the 8 chunks with __shfl_down (width 8).

#define GAMMA  0.99f
#define LMBDA  0.95f
#define GLF    (GAMMA * LMBDA)

#define B_TOT  8192
#define T_TOT  256

#define BB     8                    // sequences per block
#define NCH    8                    // chunks per sequence
#define TCH    32                   // timesteps per chunk
#define ROW_F4 (NCH * (TCH + 1))    // 264 float4 per sequence (pad 1 f4/chunk)
#define NTHREADS 256
#define F4_PER_THREAD ((BB * T_TOT) / NTHREADS)   // 8

__global__ __launch_bounds__(NTHREADS, 4)
void gae_kernel(const float4* __restrict__ reward,
                const float4* __restrict__ terminated,
                const float4* __restrict__ value,
                const float4* __restrict__ next_value,
                float4* __restrict__ adv_out,
                float4* __restrict__ ret_out)
{
    __shared__ float4 s_d[BB * ROW_F4];   // delta, then gae in-place
    __shared__ uchar4 s_f[BB * ROW_F4];   // not-done flag per element

    const int tid = threadIdx.x;
    const int b0  = blockIdx.x * BB;

    // ---------------- load + elementwise (fully coalesced) ----------------
    #pragma unroll
    for (int k = 0; k < F4_PER_THREAD; ++k) {
        const int  i   = tid + k * NTHREADS;
        const int  lbl = i >> 8;          // i / 256
        const int  t   = i & 255;
        const long g   = (long)(b0 + lbl) * T_TOT + t;

        const float4 r  = reward[g];
        const float4 tm = terminated[g];
        const float4 v  = value[g];
        const float4 nv = next_value[g];

        float4 d;
        const float ndx = 1.0f - tm.x, ndy = 1.0f - tm.y;
        const float ndz = 1.0f - tm.z, ndw = 1.0f - tm.w;
        d.x = r.x + GAMMA * nv.x * ndx - v.x;
        d.y = r.y + GAMMA * nv.y * ndy - v.y;
        d.z = r.z + GAMMA * nv.z * ndz - v.z;
        d.w = r.w + GAMMA * nv.w * ndw - v.w;

        uchar4 f;
        f.x = (unsigned char)(tm.x == 0.0f);
        f.y = (unsigned char)(tm.y == 0.0f);
        f.z = (unsigned char)(tm.z == 0.0f);
        f.w = (unsigned char)(tm.w == 0.0f);

        const int c  = t >> 5;
        const int tr = t & 31;
        const int s  = lbl * ROW_F4 + c * (TCH + 1) + tr;
        s_d[s] = d;
        s_f[s] = f;
    }
    __syncthreads();

    // ---------------- parallel scan over T ----------------
    {
        const int bl  = tid >> 5;        // sequence
        const int rem = tid & 31;
        const int a   = rem >> 3;        // agent  (lanes [8a, 8a+8) share agent)
        const int c   = rem & 7;         // chunk  (low 3 bits of lane)

        const float*         sdf = (const float*)s_d;
        const unsigned char* sff = (const unsigned char*)s_f;
        // float index and byte index coincide (both 4 scalars per f4 slot)
        const int base = bl * (ROW_F4 * 4) + c * ((TCH + 1) * 4);

        // local chunk map: gae_at_chunk_left = A + B * gae_in_from_right
        float A = 0.0f, Bc = 1.0f;
        #pragma unroll
        for (int j = TCH - 1; j >= 0; --j) {
            const int   idx = base + j * 4 + a;    // banks: (4c+4j+a)%32 distinct
            const float d   = sdf[idx];
            const float m   = sff[idx] ? GLF : 0.0f;
            A  = fmaf(m, A, d);
            Bc = m * Bc;
        }

        // suffix-compose chunk maps across c = 0..7 (inclusive suffix scan)
        #pragma unroll
        for (int off = 1; off < 8; off <<= 1) {
            const float A2 = __shfl_down_sync(0xffffffffu, A,  off, 8);
            const float B2 = __shfl_down_sync(0xffffffffu, Bc, off, 8);
            if (c + off < 8) { A = fmaf(Bc, A2, A); Bc *= B2; }
        }
        // incoming gae for chunk c = F_{c+1}(0) = A of lane c+1 ; chunk 7 gets 0
        float e = __shfl_down_sync(0xffffffffu, A, 1, 8);
        if (c == 7) e = 0.0f;

        // replay: produce gae for every t in the chunk, write back in place
        float* sdm = (float*)s_d;
        float  gae = e;
        #pragma unroll
        for (int j = TCH - 1; j >= 0; --j) {
            const int   idx = base + j * 4 + a;
            const float d   = sdm[idx];
            const float m   = sff[idx] ? GLF : 0.0f;
            gae = fmaf(m, gae, d);
            sdm[idx] = gae;
        }
    }
    __syncthreads();

    // ---------------- coalesced store (value re-read hits L1/L2) ----------------
    #pragma unroll
    for (int k = 0; k < F4_PER_THREAD; ++k) {
        const int  i   = tid + k * NTHREADS;
        const int  lbl = i >> 8;
        const int  t   = i & 255;
        const long g   = (long)(b0 + lbl) * T_TOT + t;
        const int  c   = t >> 5;
        const int  tr  = t & 31;
        const int  s   = lbl * ROW_F4 + c * (TCH + 1) + tr;

        const float4 gae = s_d[s];
        const float4 v   = value[g];
        adv_out[g] = gae;
        float4 ret;
        ret.x = gae.x + v.x; ret.y = gae.y + v.y;
        ret.z = gae.z + v.z; ret.w = gae.w + v.w;
        ret_out[g] = ret;
    }
}

extern "C" void kernel_launch(void* const* d_in, const int* in_sizes, int n_in,
                              void* d_out, int out_size)
{
    const float4* reward     = (const float4*)d_in[0];
    const float4* terminated = (const float4*)d_in[1];
    const float4* value      = (const float4*)d_in[2];
    const float4* next_value = (const float4*)d_in[3];

    const int n_elems = B_TOT * T_TOT * 4;            // 8388608 floats per tensor
    float4* adv_out = (float4*)d_out;
    float4* ret_out = (float4*)((float*)d_out + n_elems);

    dim3 grid(B_TOT / BB);     // 1024 blocks
    dim3 block(NTHREADS);      // 256 threads
    gae_kernel<<<grid, block>>>(reward, terminated, value, next_value,
                                adv_out, ret_out);
}

// round 4
// speedup vs baseline: 1.0298x; 1.0298x over previous
#include <cuda_runtime.h>

// GAE backward scan, parallel over T via affine suffix composition.
//
// gae_t = d_t + m_t * gae_{t+1},  m_t = GAMMA*LMBDA*(1-term_t)
// d_t   = r_t + GAMMA*nv_t*(1-term_t) - v_t
// adv = gae ; ret = gae + v
//
// (B=8192, T=256, A=4). One float4 = one (b,t) across 4 agents.
// Per block: BB=4 sequences, full T=256. smem stages d, m, v (fp32) so global
// traffic is exactly 4 reads + 2 writes = 201 MB. ret computed into smem
// during the scan replay; store phase is pure coalesced smem->gmem.

#define GAMMA  0.99f
#define LMBDA  0.95f
#define GLF    (GAMMA * LMBDA)

#define B_TOT  8192
#define T_TOT  256

#define BB     4                     // sequences per block
#define NCH    8                     // chunks per sequence
#define TCH    32                    // timesteps per chunk
#define ROW_F4 (NCH * (TCH + 1))     // 264 float4 per sequence (pad 1 f4/chunk)
#define ARR_F4 (BB * ROW_F4)         // 1056 float4 per array
#define NTHREADS 256
#define F4_PER_THREAD ((BB * T_TOT) / NTHREADS)   // 4

__global__ __launch_bounds__(NTHREADS, 4)
void gae_kernel(const float4* __restrict__ reward,
                const float4* __restrict__ terminated,
                const float4* __restrict__ value,
                const float4* __restrict__ next_value,
                float4* __restrict__ adv_out,
                float4* __restrict__ ret_out)
{
    extern __shared__ float4 smem[];
    float4* s_d = smem;                // delta, then gae (=adv) in-place
    float4* s_m = smem + ARR_F4;       // gamma*lambda*not_done
    float4* s_v = smem + 2 * ARR_F4;   // value, then ret in-place

    const int tid = threadIdx.x;
    const int b0  = blockIdx.x * BB;

    // ---------------- load + elementwise (fully coalesced) ----------------
    #pragma unroll
    for (int k = 0; k < F4_PER_THREAD; ++k) {
        const int  i   = tid + k * NTHREADS;
        const int  lbl = i >> 8;          // i / 256
        const int  t   = i & 255;
        const long g   = (long)(b0 + lbl) * T_TOT + t;

        const float4 r  = reward[g];
        const float4 tm = terminated[g];
        const float4 v  = value[g];
        const float4 nv = next_value[g];

        float4 d, m;
        const float ndx = 1.0f - tm.x, ndy = 1.0f - tm.y;
        const float ndz = 1.0f - tm.z, ndw = 1.0f - tm.w;
        d.x = r.x + GAMMA * nv.x * ndx - v.x;
        d.y = r.y + GAMMA * nv.y * ndy - v.y;
        d.z = r.z + GAMMA * nv.z * ndz - v.z;
        d.w = r.w + GAMMA * nv.w * ndw - v.w;
        m.x = GLF * ndx; m.y = GLF * ndy; m.z = GLF * ndz; m.w = GLF * ndw;

        const int c  = t >> 5;
        const int tr = t & 31;
        const int s  = lbl * ROW_F4 + c * (TCH + 1) + tr;
        s_d[s] = d;
        s_m[s] = m;
        s_v[s] = v;
    }
    __syncthreads();

    // ---------------- parallel scan over T (128 scan threads) ----------------
    if (tid < BB * 4 * NCH) {
        const int bl  = tid >> 5;        // sequence (0..3)
        const int rem = tid & 31;
        const int a   = rem >> 3;        // agent (lanes [8a,8a+8) share agent)
        const int c   = rem & 7;         // chunk

        const float* sdf = (const float*)s_d;
        const float* smf = (const float*)s_m;
        // base in floats; banks: (4c + 4j + a) % 32 -> conflict-free per warp
        const int base = bl * (ROW_F4 * 4) + c * ((TCH + 1) * 4);

        // local chunk map: gae_at_left = A + B * gae_in_from_right
        float A = 0.0f, Bc = 1.0f;
        #pragma unroll
        for (int j = TCH - 1; j >= 0; --j) {
            const int   idx = base + j * 4 + a;
            const float d   = sdf[idx];
            const float m   = smf[idx];
            A  = fmaf(m, A, d);
            Bc = m * Bc;
        }

        // suffix-compose across the 8 chunks (groups of 8 lanes)
        #pragma unroll
        for (int off = 1; off < 8; off <<= 1) {
            const float A2 = __shfl_down_sync(0xffffffffu, A,  off, 8);
            const float B2 = __shfl_down_sync(0xffffffffu, Bc, off, 8);
            if (c + off < 8) { A = fmaf(Bc, A2, A); Bc *= B2; }
        }
        float e = __shfl_down_sync(0xffffffffu, A, 1, 8);
        if (c == 7) e = 0.0f;

        // replay: gae -> s_d in place, ret = gae + v -> s_v in place
        float* sdm = (float*)s_d;
        float* svm = (float*)s_v;
        float  gae = e;
        #pragma unroll
        for (int j = TCH - 1; j >= 0; --j) {
            const int   idx = base + j * 4 + a;
            const float d   = sdm[idx];
            const float m   = smf[idx];
            gae = fmaf(m, gae, d);
            sdm[idx] = gae;
            svm[idx] = gae + svm[idx];
        }
    }
    __syncthreads();

    // ---------------- coalesced store ----------------
    #pragma unroll
    for (int k = 0; k < F4_PER_THREAD; ++k) {
        const int  i   = tid + k * NTHREADS;
        const int  lbl = i >> 8;
        const int  t   = i & 255;
        const long g   = (long)(b0 + lbl) * T_TOT + t;
        const int  c   = t >> 5;
        const int  tr  = t & 31;
        const int  s   = lbl * ROW_F4 + c * (TCH + 1) + tr;

        adv_out[g] = s_d[s];
        ret_out[g] = s_v[s];
    }
}

extern "C" void kernel_launch(void* const* d_in, const int* in_sizes, int n_in,
                              void* d_out, int out_size)
{
    const float4* reward     = (const float4*)d_in[0];
    const float4* terminated = (const float4*)d_in[1];
    const float4* value      = (const float4*)d_in[2];
    const float4* next_value = (const float4*)d_in[3];

    const int n_elems = B_TOT * T_TOT * 4;            // floats per tensor
    float4* adv_out = (float4*)d_out;
    float4* ret_out = (float4*)((float*)d_out + n_elems);

    const size_t smem_bytes = 3 * ARR_F4 * sizeof(float4);   // 50688 B
    cudaFuncSetAttribute(gae_kernel,
                         cudaFuncAttributeMaxDynamicSharedMemorySize,
                         (int)smem_bytes);

    dim3 grid(B_TOT / BB);     // 2048 blocks
    dim3 block(NTHREADS);      // 256 threads
    gae_kernel<<<grid, block, smem_bytes>>>(reward, terminated, value, next_value,
                                            adv_out, ret_out);
}

// round 5
// speedup vs baseline: 1.4543x; 1.4121x over previous
#include <cuda_runtime.h>

// GAE backward scan — warp-per-sequence, register-resident, no smem/barriers.
//
// gae_t = d_t + m_t * gae_{t+1},  m_t = GAMMA*LMBDA*(1-term_t)
// d_t   = r_t + GAMMA*nv_t*(1-term_t) - v_t
// adv = gae ; ret = gae + v
//
// (B=8192, T=256, A=4). One float4 = one (b,t) across 4 agents; consecutive t
// are contiguous float4s, so lane l <-> timestep gives 512B coalesced LDG/STG.
// Each warp owns one sequence: 8 chunks of 32 timesteps, processed backward.
// Per chunk: warp-wide suffix scan of affine maps (A,B) via shfl_down
//   (gae_l = A_l + B_l * gae_incoming), then combine with the carry and
//   broadcast lane 0's gae as carry for the next (earlier) chunk.
// Chunk loads are carry-independent -> overlap across iterations.

#define GAMMA  0.99f
#define LMBDA  0.95f
#define GLF    (GAMMA * LMBDA)

#define B_TOT  8192
#define T_TOT  256
#define NTHREADS 256
#define WARPS_PER_BLOCK (NTHREADS / 32)

__device__ __forceinline__ float4 ldcs4(const float4* p) {
    return __ldcs(p);
}

__global__ __launch_bounds__(NTHREADS, 3)
void gae_kernel(const float4* __restrict__ reward,
                const float4* __restrict__ terminated,
                const float4* __restrict__ value,
                const float4* __restrict__ next_value,
                float4* __restrict__ adv_out,
                float4* __restrict__ ret_out)
{
    const int warp = blockIdx.x * WARPS_PER_BLOCK + (threadIdx.x >> 5);
    const int lane = threadIdx.x & 31;
    const long base = (long)warp * T_TOT;   // sequence start (in float4 units)

    float cx = 0.0f, cy = 0.0f, cz = 0.0f, cw = 0.0f;   // gae carry

    #pragma unroll
    for (int c = T_TOT / 32 - 1; c >= 0; --c) {
        const long g = base + c * 32 + lane;

        const float4 r  = ldcs4(reward     + g);
        const float4 tm = ldcs4(terminated + g);
        const float4 v  = ldcs4(value      + g);
        const float4 nv = ldcs4(next_value + g);

        // per-lane affine map: gae_here = A + B * gae_from_right
        const float ndx = 1.0f - tm.x, ndy = 1.0f - tm.y;
        const float ndz = 1.0f - tm.z, ndw = 1.0f - tm.w;

        float Ax = r.x + GAMMA * nv.x * ndx - v.x;
        float Ay = r.y + GAMMA * nv.y * ndy - v.y;
        float Az = r.z + GAMMA * nv.z * ndz - v.z;
        float Aw = r.w + GAMMA * nv.w * ndw - v.w;
        float Bx = GLF * ndx, By = GLF * ndy, Bz = GLF * ndz, Bw = GLF * ndw;

        // warp suffix scan of affine composition: lane l ends covering [l, 31]
        #pragma unroll
        for (int off = 1; off < 32; off <<= 1) {
            const float A2x = __shfl_down_sync(0xffffffffu, Ax, off);
            const float A2y = __shfl_down_sync(0xffffffffu, Ay, off);
            const float A2z = __shfl_down_sync(0xffffffffu, Az, off);
            const float A2w = __shfl_down_sync(0xffffffffu, Aw, off);
            const float B2x = __shfl_down_sync(0xffffffffu, Bx, off);
            const float B2y = __shfl_down_sync(0xffffffffu, By, off);
            const float B2z = __shfl_down_sync(0xffffffffu, Bz, off);
            const float B2w = __shfl_down_sync(0xffffffffu, Bw, off);
            if (lane + off < 32) {
                Ax = fmaf(Bx, A2x, Ax);  Bx *= B2x;
                Ay = fmaf(By, A2y, Ay);  By *= B2y;
                Az = fmaf(Bz, A2z, Az);  Bz *= B2z;
                Aw = fmaf(Bw, A2w, Aw);  Bw *= B2w;
            }
        }

        // apply carry entering from the right edge of this chunk
        float4 gae;
        gae.x = fmaf(Bx, cx, Ax);
        gae.y = fmaf(By, cy, Ay);
        gae.z = fmaf(Bz, cz, Az);
        gae.w = fmaf(Bw, cw, Aw);

        // outputs (streaming stores)
        __stcs(adv_out + g, gae);
        float4 ret;
        ret.x = gae.x + v.x; ret.y = gae.y + v.y;
        ret.z = gae.z + v.z; ret.w = gae.w + v.w;
        __stcs(ret_out + g, ret);

        // carry for next (earlier) chunk = gae at this chunk's t0 (lane 0)
        cx = __shfl_sync(0xffffffffu, gae.x, 0);
        cy = __shfl_sync(0xffffffffu, gae.y, 0);
        cz = __shfl_sync(0xffffffffu, gae.z, 0);
        cw = __shfl_sync(0xffffffffu, gae.w, 0);
    }
}

extern "C" void kernel_launch(void* const* d_in, const int* in_sizes, int n_in,
                              void* d_out, int out_size)
{
    const float4* reward     = (const float4*)d_in[0];
    const float4* terminated = (const float4*)d_in[1];
    const float4* value      = (const float4*)d_in[2];
    const float4* next_value = (const float4*)d_in[3];

    const int n_elems = B_TOT * T_TOT * 4;            // floats per tensor
    float4* adv_out = (float4*)d_out;
    float4* ret_out = (float4*)((float*)d_out + n_elems);

    dim3 grid(B_TOT / WARPS_PER_BLOCK);   // 1024 blocks (8 warps = 8 sequences each)
    dim3 block(NTHREADS);
    gae_kernel<<<grid, block>>>(reward, terminated, value, next_value,
                                adv_out, ret_out);
}

// round 6
// speedup vs baseline: 1.5377x; 1.0574x over previous
#include <cuda_runtime.h>

// GAE backward scan — warp-per-sequence, register-resident, software-pipelined.
//
// gae_t = d_t + m_t * gae_{t+1},  m_t = GAMMA*LMBDA*(1-term_t)
// d_t   = r_t + GAMMA*nv_t*(1-term_t) - v_t
// adv = gae ; ret = gae + v
//
// (B=8192, T=256, A=4). One float4 = one (b,t) across 4 agents; lane l <->
// timestep gives 512B fully coalesced LDG/STG. Each warp owns one sequence:
// 8 chunks of 32 timesteps backward; per chunk a warp-wide suffix scan of
// affine maps (A,B) via shfl_down. The next chunk's 4 loads are issued BEFORE
// the current chunk's scan (they don't depend on the carry), so LDG latency
// hides under the shuffle chain.

#define GAMMA  0.99f
#define LMBDA  0.95f
#define GLF    (GAMMA * LMBDA)

#define B_TOT  8192
#define T_TOT  256
#define NTHREADS 128
#define WARPS_PER_BLOCK (NTHREADS / 32)

__global__ __launch_bounds__(NTHREADS, 8)
void gae_kernel(const float4* __restrict__ reward,
                const float4* __restrict__ terminated,
                const float4* __restrict__ value,
                const float4* __restrict__ next_value,
                float4* __restrict__ adv_out,
                float4* __restrict__ ret_out)
{
    const int warp = blockIdx.x * WARPS_PER_BLOCK + (threadIdx.x >> 5);
    const int lane = threadIdx.x & 31;
    const long base = (long)warp * T_TOT + lane;   // float4 units

    float cx = 0.0f, cy = 0.0f, cz = 0.0f, cw = 0.0f;   // gae carry

    // prefetch chunk 7
    float4 r  = __ldcs(reward     + base + 7 * 32);
    float4 tm = __ldcs(terminated + base + 7 * 32);
    float4 v  = __ldcs(value      + base + 7 * 32);
    float4 nv = __ldcs(next_value + base + 7 * 32);

    #pragma unroll
    for (int c = T_TOT / 32 - 1; c >= 0; --c) {
        // consume current chunk's raw data
        const float4 rr = r, tt = tm, vv = v, nn = nv;

        // issue next (earlier) chunk's loads now — independent of the scan
        if (c > 0) {
            const long g2 = base + (c - 1) * 32;
            r  = __ldcs(reward     + g2);
            tm = __ldcs(terminated + g2);
            v  = __ldcs(value      + g2);
            nv = __ldcs(next_value + g2);
        }

        // per-lane affine map: gae_here = A + B * gae_from_right
        const float ndx = 1.0f - tt.x, ndy = 1.0f - tt.y;
        const float ndz = 1.0f - tt.z, ndw = 1.0f - tt.w;

        float Ax = rr.x + GAMMA * nn.x * ndx - vv.x;
        float Ay = rr.y + GAMMA * nn.y * ndy - vv.y;
        float Az = rr.z + GAMMA * nn.z * ndz - vv.z;
        float Aw = rr.w + GAMMA * nn.w * ndw - vv.w;
        float Bx = GLF * ndx, By = GLF * ndy, Bz = GLF * ndz, Bw = GLF * ndw;

        // warp suffix scan of affine composition: lane l ends covering [l, 31]
        #pragma unroll
        for (int off = 1; off < 32; off <<= 1) {
            const float A2x = __shfl_down_sync(0xffffffffu, Ax, off);
            const float A2y = __shfl_down_sync(0xffffffffu, Ay, off);
            const float A2z = __shfl_down_sync(0xffffffffu, Az, off);
            const float A2w = __shfl_down_sync(0xffffffffu, Aw, off);
            const float B2x = __shfl_down_sync(0xffffffffu, Bx, off);
            const float B2y = __shfl_down_sync(0xffffffffu, By, off);
            const float B2z = __shfl_down_sync(0xffffffffu, Bz, off);
            const float B2w = __shfl_down_sync(0xffffffffu, Bw, off);
            if (lane + off < 32) {
                Ax = fmaf(Bx, A2x, Ax);  Bx *= B2x;
                Ay = fmaf(By, A2y, Ay);  By *= B2y;
                Az = fmaf(Bz, A2z, Az);  Bz *= B2z;
                Aw = fmaf(Bw, A2w, Aw);  Bw *= B2w;
            }
        }

        // apply the carry entering from the right edge of this chunk
        float4 gae;
        gae.x = fmaf(Bx, cx, Ax);
        gae.y = fmaf(By, cy, Ay);
        gae.z = fmaf(Bz, cz, Az);
        gae.w = fmaf(Bw, cw, Aw);

        // streaming stores
        const long g = base + c * 32;
        __stcs(adv_out + g, gae);
        float4 ret;
        ret.x = gae.x + vv.x; ret.y = gae.y + vv.y;
        ret.z = gae.z + vv.z; ret.w = gae.w + vv.w;
        __stcs(ret_out + g, ret);

        // carry for next (earlier) chunk = gae at this chunk's t0 (lane 0)
        cx = __shfl_sync(0xffffffffu, gae.x, 0);
        cy = __shfl_sync(0xffffffffu, gae.y, 0);
        cz = __shfl_sync(0xffffffffu, gae.z, 0);
        cw = __shfl_sync(0xffffffffu, gae.w, 0);
    }
}

extern "C" void kernel_launch(void* const* d_in, const int* in_sizes, int n_in,
                              void* d_out, int out_size)
{
    const float4* reward     = (const float4*)d_in[0];
    const float4* terminated = (const float4*)d_in[1];
    const float4* value      = (const float4*)d_in[2];
    const float4* next_value = (const float4*)d_in[3];

    const int n_elems = B_TOT * T_TOT * 4;            // floats per tensor
    float4* adv_out = (float4*)d_out;
    float4* ret_out = (float4*)((float*)d_out + n_elems);

    dim3 grid(B_TOT / WARPS_PER_BLOCK);   // 2048 blocks, 4 warps each
    dim3 block(NTHREADS);
    gae_kernel<<<grid, block>>>(reward, terminated, value, next_value,
                                adv_out, ret_out);
}

// round 7
// speedup vs baseline: 1.7286x; 1.1242x over previous
#include <cuda_runtime.h>

// GAE backward scan — warp-per-sequence, segmented-suffix-sum formulation.
//
// gae_t = d_t + m_t*gae_{t+1},  m_t = GL*(1-term_t), term ∈ {0,1} exactly.
// Key: m is binary-valued -> the propagation structure is a termination
// bitmask (one ballot per agent). With w_l = d_l*GL^l the within-chunk scan
// is a PLAIN suffix sum (5 shuffles/agent); segment edges are resolved by a
// single variable-index shuffle: gae_l = (S_l - S_{e_l+1}) * GL^{-l} (+carry).
//
// (B=8192, T=256, A=4). One float4 = one (b,t) across 4 agents; lane <-> t
// gives fully coalesced 512B LDG/STG. 8 chunks of 32 backward per warp,
// next chunk's loads issued before the current scan (carry-independent).

#define GAMMA  0.99f
#define LMBDA  0.95f
#define GLF    (GAMMA * LMBDA)

#define B_TOT  8192
#define T_TOT  256
#define NTHREADS 128
#define WARPS_PER_BLOCK (NTHREADS / 32)
#define FULL 0xffffffffu

// one agent's segmented suffix scan for a 32-step chunk
// w      : d_l * GL^l   (pre-scaled delta)
// M      : termination bitmask for this agent (bit l = terminated at step l)
// carry  : gae entering from the right edge (t = chunk_end)
// returns gae_l
__device__ __forceinline__ float comp_gae(float w, unsigned M, float carry,
                                          int lane, float invglp, float gl32)
{
    // plain suffix sum S_l = sum_{j>=l} w_j
    float S = w;
    #pragma unroll
    for (int off = 1; off < 32; off <<= 1) {
        const float t = __shfl_down_sync(FULL, S, off);
        if (lane + off < 32) S += t;
    }

    // first termination at or after this lane bounds the segment
    const unsigned Mge = M >> lane;
    const int src = Mge ? (lane + __ffs(Mge)) : 32;   // e_l + 1
    const float Sg = __shfl_sync(FULL, S, src);       // clamped if src==32
    float acc = S - (src < 32 ? Sg : 0.0f);
    if (!Mge) acc = fmaf(carry, gl32, acc);           // carry reaches only unbroken suffixes
    return acc * invglp;
}

__global__ __launch_bounds__(NTHREADS, 8)
void gae_kernel(const float4* __restrict__ reward,
                const float4* __restrict__ terminated,
                const float4* __restrict__ value,
                const float4* __restrict__ next_value,
                float4* __restrict__ adv_out,
                float4* __restrict__ ret_out)
{
    const int warp = blockIdx.x * WARPS_PER_BLOCK + (threadIdx.x >> 5);
    const int lane = threadIdx.x & 31;
    const long base = (long)warp * T_TOT + lane;   // float4 units

    // per-lane scale constants
    const float glp    = __powf(GLF, (float)lane);   // GL^lane
    const float invglp = 1.0f / glp;                 // GL^-lane
    const float gl32   = __powf(GLF, 32.0f);         // GL^32

    float cx = 0.0f, cy = 0.0f, cz = 0.0f, cw = 0.0f;   // gae carry

    // prefetch chunk 7
    float4 r  = __ldcs(reward     + base + 7 * 32);
    float4 tm = __ldcs(terminated + base + 7 * 32);
    float4 v  = __ldcs(value      + base + 7 * 32);
    float4 nv = __ldcs(next_value + base + 7 * 32);

    #pragma unroll
    for (int c = T_TOT / 32 - 1; c >= 0; --c) {
        const float4 rr = r, tt = tm, vv = v, nn = nv;

        // issue next (earlier) chunk's loads — independent of the scan
        if (c > 0) {
            const long g2 = base + (c - 1) * 32;
            r  = __ldcs(reward     + g2);
            tm = __ldcs(terminated + g2);
            v  = __ldcs(value      + g2);
            nv = __ldcs(next_value + g2);
        }

        // termination masks (one ballot per agent)
        const unsigned Mx = __ballot_sync(FULL, tt.x != 0.0f);
        const unsigned My = __ballot_sync(FULL, tt.y != 0.0f);
        const unsigned Mz = __ballot_sync(FULL, tt.z != 0.0f);
        const unsigned Mw = __ballot_sync(FULL, tt.w != 0.0f);

        // deltas, pre-scaled by GL^lane
        const float ndx = 1.0f - tt.x, ndy = 1.0f - tt.y;
        const float ndz = 1.0f - tt.z, ndw = 1.0f - tt.w;
        const float wx = (rr.x + GAMMA * nn.x * ndx - vv.x) * glp;
        const float wy = (rr.y + GAMMA * nn.y * ndy - vv.y) * glp;
        const float wz = (rr.z + GAMMA * nn.z * ndz - vv.z) * glp;
        const float ww = (rr.w + GAMMA * nn.w * ndw - vv.w) * glp;

        float4 gae;
        gae.x = comp_gae(wx, Mx, cx, lane, invglp, gl32);
        gae.y = comp_gae(wy, My, cy, lane, invglp, gl32);
        gae.z = comp_gae(wz, Mz, cz, lane, invglp, gl32);
        gae.w = comp_gae(ww, Mw, cw, lane, invglp, gl32);

        // streaming stores
        const long g = base + c * 32;
        __stcs(adv_out + g, gae);
        float4 ret;
        ret.x = gae.x + vv.x; ret.y = gae.y + vv.y;
        ret.z = gae.z + vv.z; ret.w = gae.w + vv.w;
        __stcs(ret_out + g, ret);

        // carry for the next (earlier) chunk = gae at this chunk's first step
        cx = __shfl_sync(FULL, gae.x, 0);
        cy = __shfl_sync(FULL, gae.y, 0);
        cz = __shfl_sync(FULL, gae.z, 0);
        cw = __shfl_sync(FULL, gae.w, 0);
    }
}

extern "C" void kernel_launch(void* const* d_in, const int* in_sizes, int n_in,
                              void* d_out, int out_size)
{
    const float4* reward     = (const float4*)d_in[0];
    const float4* terminated = (const float4*)d_in[1];
    const float4* value      = (const float4*)d_in[2];
    const float4* next_value = (const float4*)d_in[3];

    const int n_elems = B_TOT * T_TOT * 4;            // floats per tensor
    float4* adv_out = (float4*)d_out;
    float4* ret_out = (float4*)((float*)d_out + n_elems);

    dim3 grid(B_TOT / WARPS_PER_BLOCK);   // 2048 blocks, 4 warps each
    dim3 block(NTHREADS);
    gae_kernel<<<grid, block>>>(reward, terminated, value, next_value,
                                adv_out, ret_out);
}